// round 12
// baseline (speedup 1.0000x reference)
#include <cuda_runtime.h>
#include <cuda_bf16.h>

// DistMult scoring: out[b] = sum_d src[b,d] * M[rel_idx, d] * dst[b,d]
// B = 500000, D = 128. HBM-bound stream (~514 MB traffic).
//
// Persistent grid-stride design:
//   - grid = 148 SMs * 8 CTAs, 256 thr each -> 7104 warps, ~70 rows per warp.
//   - one warp per row, lane l owns float4 #l of the row (fully coalesced:
//     warp reads contiguous 512 B per tensor per row).
//   - software pipelining: next row's src/dst LDG.128 issue BEFORE the current
//     row's FMA + 5-shuffle reduction, so loads are continuously in flight
//     across the whole kernel (no CTA-exit / launch bubbles).
//   - M[rel] float4 is loop-invariant: loaded once per warp.

__global__ __launch_bounds__(256) void distmult_kernel(
    const float4* __restrict__ src4,
    const float4* __restrict__ dst4,
    const float4* __restrict__ M4,
    const int* __restrict__ rel_idx,
    float* __restrict__ out,
    int B)
{
    const int lane = threadIdx.x & 31;
    const int warp_global = (blockIdx.x * blockDim.x + threadIdx.x) >> 5;
    const int nwarps = (gridDim.x * blockDim.x) >> 5;

    const int r = __ldg(rel_idx);
    const float4 m = __ldg(&M4[(long)r * 32 + lane]);   // loop-invariant

    long row = warp_global;
    if (row >= B) return;

    // prologue load
    float4 s = __ldcs(&src4[row * 32 + lane]);
    float4 d = __ldcs(&dst4[row * 32 + lane]);

    for (;;) {
        const long next = row + nwarps;
        const bool have_next = next < B;

        // prefetch next iteration's data before touching current (keeps
        // LDGs in flight during the FMA + shuffle chain below)
        float4 s2, d2;
        if (have_next) {
            s2 = __ldcs(&src4[next * 32 + lane]);
            d2 = __ldcs(&dst4[next * 32 + lane]);
        }

        float p = s.x * m.x * d.x;
        p = fmaf(s.y * m.y, d.y, p);
        p = fmaf(s.z * m.z, d.z, p);
        p = fmaf(s.w * m.w, d.w, p);

        #pragma unroll
        for (int off = 16; off > 0; off >>= 1)
            p += __shfl_xor_sync(0xffffffffu, p, off);

        if (lane == 0) out[row] = p;

        if (!have_next) break;
        s = s2; d = d2; row = next;
    }
}

extern "C" void kernel_launch(void* const* d_in, const int* in_sizes, int n_in,
                              void* d_out, int out_size)
{
    // metadata order: src_emb [B,128] f32, dst_emb [B,128] f32, M [1000,128] f32, rel_idx int32
    const float4* src4 = (const float4*)d_in[0];
    const float4* dst4 = (const float4*)d_in[1];
    const float4* M4   = (const float4*)d_in[2];
    const int* rel_idx = (const int*)d_in[3];
    float* out = (float*)d_out;

    const int B = in_sizes[0] / 128;   // 500000

    // persistent: 8 CTAs per SM on 148 SMs (fits: ~30 regs/thread)
    const int blocks = 148 * 8;
    distmult_kernel<<<blocks, 256>>>(src4, dst4, M4, rel_idx, out, B);
}